// round 1
// baseline (speedup 1.0000x reference)
#include <cuda_runtime.h>
#include <math.h>

#define NTOK 98304              // B*M = 16384*6
#define EXP 6
#define TRAJ_LEN (NTOK*120)     // [B,M,T,2] = 11796480
#define SCORE_OFF TRAJ_LEN
#define AUX_OFF   (SCORE_OFF + NTOK)
#define PROBS_OFF (AUX_OFF + 1)

// ---------------- scratch (device globals; no allocation allowed) ----------
__device__ float g_H1[NTOK*256];     // router hidden 1
__device__ float g_H2[NTOK*128];     // router hidden 2
__device__ float g_G1[NTOK*256];     // expert traj hidden 1 (reused per expert)
__device__ float g_G2[NTOK*256];     // expert traj hidden 2
__device__ float g_S1[NTOK*128];     // expert score hidden 1
__device__ float g_S2[NTOK*64];      // expert score hidden 2
__device__ int   g_list[EXP*NTOK];   // token indices per expert
__device__ float g_wlist[EXP*NTOK];  // gate weight per (expert, slot)
__device__ int   g_cnt[8];           // tokens per expert
__device__ float g_partials[256*6];  // aux-loss partial sums

__device__ __forceinline__ float gelu_exact(float x) {
    return 0.5f * x * (1.0f + erff(x * 0.7071067811865476f));
}

// ---------------- init: zero accumulated output regions + counters ---------
__global__ void init_kernel(float* __restrict__ out) {
    long i = (long)blockIdx.x * blockDim.x + threadIdx.x;   // 11616*256 threads
    ((float4*)out)[i] = make_float4(0.f, 0.f, 0.f, 0.f);    // covers traj+scores
    if (blockIdx.x == 0 && threadIdx.x < 8) g_cnt[threadIdx.x] = 0;
}

// ---------------- generic tiled GEMM: C = act(A @ W + bias) ----------------
// A: [M,K] row-major (optionally gathered rows), W: [K,N] row-major.
// BM=BN=64, BK=16, 256 threads, 4x4 microtile.
template<bool GELU_ACT, bool GATHER>
__global__ __launch_bounds__(256) void gemm_kernel(
    const float* __restrict__ A, int lda,
    const float* __restrict__ W, int ldw,
    const float* __restrict__ bias,
    float* __restrict__ C, int ldc,
    int Ncols, int Kdim,
    const int* __restrict__ gather,
    const int* __restrict__ cntPtr, int Mfixed)
{
    int Mrows = cntPtr ? *cntPtr : Mfixed;
    int rowBase = blockIdx.y << 6;
    if (rowBase >= Mrows) return;
    int colBase = blockIdx.x << 6;

    __shared__ float As[16][64];
    __shared__ float Ws[16][64];

    int t  = threadIdx.x;
    int tx = t & 15, ty = t >> 4;

    // A-tile loader: thread covers (row mA, k-quad kqA)
    int mA = t & 63, kqA = t >> 6;
    int rowA = rowBase + mA;
    bool rowValid = rowA < Mrows;
    long arow = rowValid ? (GATHER ? (long)gather[rowA] : (long)rowA) : 0;
    const float* Aptr = A + arow * (long)lda;

    // W-tile loader
    int kW = t >> 4;
    int nW = (t & 15) << 2;
    int ncol = colBase + nW;
    bool colValid = ncol < Ncols;

    float acc[4][4];
#pragma unroll
    for (int i = 0; i < 4; i++)
#pragma unroll
        for (int j = 0; j < 4; j++) acc[i][j] = 0.f;

    for (int k0 = 0; k0 < Kdim; k0 += 16) {
        float4 av = rowValid ? *(const float4*)(Aptr + k0 + (kqA << 2))
                             : make_float4(0.f, 0.f, 0.f, 0.f);
        As[(kqA << 2) + 0][mA] = av.x;
        As[(kqA << 2) + 1][mA] = av.y;
        As[(kqA << 2) + 2][mA] = av.z;
        As[(kqA << 2) + 3][mA] = av.w;
        float4 wv = colValid ? *(const float4*)(W + (long)(k0 + kW) * ldw + ncol)
                             : make_float4(0.f, 0.f, 0.f, 0.f);
        *(float4*)&Ws[kW][nW] = wv;
        __syncthreads();
#pragma unroll
        for (int kk = 0; kk < 16; kk++) {
            float4 a = *(const float4*)&As[kk][ty << 2];
            float4 b = *(const float4*)&Ws[kk][tx << 2];
            acc[0][0] += a.x * b.x; acc[0][1] += a.x * b.y; acc[0][2] += a.x * b.z; acc[0][3] += a.x * b.w;
            acc[1][0] += a.y * b.x; acc[1][1] += a.y * b.y; acc[1][2] += a.y * b.z; acc[1][3] += a.y * b.w;
            acc[2][0] += a.z * b.x; acc[2][1] += a.z * b.y; acc[2][2] += a.z * b.z; acc[2][3] += a.z * b.w;
            acc[3][0] += a.w * b.x; acc[3][1] += a.w * b.y; acc[3][2] += a.w * b.z; acc[3][3] += a.w * b.w;
        }
        __syncthreads();
    }

    float bi[4];
#pragma unroll
    for (int j = 0; j < 4; j++) {
        int c = colBase + (tx << 2) + j;
        bi[j] = (c < Ncols) ? bias[c] : 0.f;
    }
#pragma unroll
    for (int i = 0; i < 4; i++) {
        int r = rowBase + (ty << 2) + i;
        if (r >= Mrows) continue;
        float* Crow = C + (long)r * ldc;
#pragma unroll
        for (int j = 0; j < 4; j++) {
            int c = colBase + (tx << 2) + j;
            if (c < Ncols) {
                float v = acc[i][j] + bi[j];
                if (GELU_ACT) v = gelu_exact(v);
                Crow[c] = v;
            }
        }
    }
}

// ---------------- traj final layer: GEMM + weighted scatter-add ------------
// out[token*120 + c] += w_slot * (G2[slot] @ W3 + b3)[c]
__global__ __launch_bounds__(256) void gemm_scatter_kernel(
    const float* __restrict__ A, int lda,
    const float* __restrict__ W, int ldw,
    const float* __restrict__ bias,
    float* __restrict__ out,
    int Ncols, int Kdim,
    const int* __restrict__ list,
    const float* __restrict__ wlist,
    const int* __restrict__ cntPtr)
{
    int Mrows = *cntPtr;
    int rowBase = blockIdx.y << 6;
    if (rowBase >= Mrows) return;
    int colBase = blockIdx.x << 6;

    __shared__ float As[16][64];
    __shared__ float Ws[16][64];

    int t  = threadIdx.x;
    int tx = t & 15, ty = t >> 4;

    int mA = t & 63, kqA = t >> 6;
    int rowA = rowBase + mA;
    bool rowValid = rowA < Mrows;
    const float* Aptr = A + (rowValid ? (long)rowA : 0L) * (long)lda;

    int kW = t >> 4;
    int nW = (t & 15) << 2;
    int ncol = colBase + nW;
    bool colValid = ncol < Ncols;

    float acc[4][4];
#pragma unroll
    for (int i = 0; i < 4; i++)
#pragma unroll
        for (int j = 0; j < 4; j++) acc[i][j] = 0.f;

    for (int k0 = 0; k0 < Kdim; k0 += 16) {
        float4 av = rowValid ? *(const float4*)(Aptr + k0 + (kqA << 2))
                             : make_float4(0.f, 0.f, 0.f, 0.f);
        As[(kqA << 2) + 0][mA] = av.x;
        As[(kqA << 2) + 1][mA] = av.y;
        As[(kqA << 2) + 2][mA] = av.z;
        As[(kqA << 2) + 3][mA] = av.w;
        float4 wv = colValid ? *(const float4*)(W + (long)(k0 + kW) * ldw + ncol)
                             : make_float4(0.f, 0.f, 0.f, 0.f);
        *(float4*)&Ws[kW][nW] = wv;
        __syncthreads();
#pragma unroll
        for (int kk = 0; kk < 16; kk++) {
            float4 a = *(const float4*)&As[kk][ty << 2];
            float4 b = *(const float4*)&Ws[kk][tx << 2];
            acc[0][0] += a.x * b.x; acc[0][1] += a.x * b.y; acc[0][2] += a.x * b.z; acc[0][3] += a.x * b.w;
            acc[1][0] += a.y * b.x; acc[1][1] += a.y * b.y; acc[1][2] += a.y * b.z; acc[1][3] += a.y * b.w;
            acc[2][0] += a.z * b.x; acc[2][1] += a.z * b.y; acc[2][2] += a.z * b.z; acc[2][3] += a.z * b.w;
            acc[3][0] += a.w * b.x; acc[3][1] += a.w * b.y; acc[3][2] += a.w * b.z; acc[3][3] += a.w * b.w;
        }
        __syncthreads();
    }

    float bi[4];
#pragma unroll
    for (int j = 0; j < 4; j++) {
        int c = colBase + (tx << 2) + j;
        bi[j] = (c < Ncols) ? bias[c] : 0.f;
    }
#pragma unroll
    for (int i = 0; i < 4; i++) {
        int slot = rowBase + (ty << 2) + i;
        if (slot >= Mrows) continue;
        int token = list[slot];
        float w   = wlist[slot];
        float* orow = out + (long)token * 120;
#pragma unroll
        for (int j = 0; j < 4; j++) {
            int c = colBase + (tx << 2) + j;
            if (c < Ncols) atomicAdd(&orow[c], w * (acc[i][j] + bi[j]));
        }
    }
}

// ---------------- router tail: logits -> probs, top-2 gate, expert lists ---
__global__ __launch_bounds__(256) void router_tail(
    const float* __restrict__ H2,
    const float* __restrict__ W3,   // [128,6]
    const float* __restrict__ b3,   // [6]
    float* __restrict__ probs_out,  // [NTOK,6]
    int*   __restrict__ lists,
    float* __restrict__ wlists,
    int*   __restrict__ cnts)
{
    __shared__ float sW[128*6];
    __shared__ float sb[6];
    for (int i = threadIdx.x; i < 128*6; i += 256) sW[i] = W3[i];
    if (threadIdx.x < 6) sb[threadIdx.x] = b3[threadIdx.x];
    __syncthreads();

    int warp = threadIdx.x >> 5;
    int lane = threadIdx.x & 31;
    int token = blockIdx.x * 8 + warp;
    if (token >= NTOK) return;

    const float* h = H2 + (long)token * 128;
    float acc[6] = {0.f, 0.f, 0.f, 0.f, 0.f, 0.f};
#pragma unroll
    for (int j = 0; j < 4; j++) {
        int k = lane + 32 * j;
        float xv = h[k];
#pragma unroll
        for (int e = 0; e < 6; e++) acc[e] += xv * sW[k*6 + e];
    }
#pragma unroll
    for (int off = 16; off; off >>= 1)
#pragma unroll
        for (int e = 0; e < 6; e++) acc[e] += __shfl_xor_sync(0xffffffffu, acc[e], off);

    if (lane == 0) {
        float logits[6];
#pragma unroll
        for (int e = 0; e < 6; e++) logits[e] = acc[e] + sb[e];
        // full softmax -> probs
        float mx = logits[0];
#pragma unroll
        for (int e = 1; e < 6; e++) mx = fmaxf(mx, logits[e]);
        float p[6], s = 0.f;
#pragma unroll
        for (int e = 0; e < 6; e++) { p[e] = expf(logits[e] - mx); s += p[e]; }
        float inv = 1.f / s;
#pragma unroll
        for (int e = 0; e < 6; e++) probs_out[(long)token*6 + e] = p[e] * inv;
        // top-2 (ties -> lowest index, matching lax.top_k)
        int i0 = 0;
#pragma unroll
        for (int e = 1; e < 6; e++) if (logits[e] > logits[i0]) i0 = e;
        int i1 = (i0 == 0) ? 1 : 0;
#pragma unroll
        for (int e = 0; e < 6; e++)
            if (e != i0 && logits[e] > logits[i1]) i1 = e;
        float r  = expf(logits[i1] - logits[i0]);
        float w0 = 1.f / (1.f + r);
        float w1 = r / (1.f + r);
        int s0 = atomicAdd(&cnts[i0], 1);
        lists[i0*NTOK + s0] = token;  wlists[i0*NTOK + s0] = w0;
        int s1 = atomicAdd(&cnts[i1], 1);
        lists[i1*NTOK + s1] = token;  wlists[i1*NTOK + s1] = w1;
    }
}

// ---------------- score tail: dot(S2[slot], W3) + b; scatter-add -----------
__global__ __launch_bounds__(256) void score_tail(
    const float* __restrict__ S2,
    const float* __restrict__ W3,   // [64]
    const float* __restrict__ b3,   // [1]
    const int*   __restrict__ list,
    const float* __restrict__ wlist,
    const int*   __restrict__ cntPtr,
    float* __restrict__ out_scores)
{
    __shared__ float sW[64];
    if (threadIdx.x < 64) sW[threadIdx.x] = W3[threadIdx.x];
    __syncthreads();
    int cnt = *cntPtr;
    int warp = threadIdx.x >> 5;
    int lane = threadIdx.x & 31;
    int slot = blockIdx.x * 8 + warp;
    if (slot >= cnt) return;
    const float* row = S2 + (long)slot * 64;
    float a = row[lane] * sW[lane] + row[lane + 32] * sW[lane + 32];
#pragma unroll
    for (int off = 16; off; off >>= 1) a += __shfl_xor_sync(0xffffffffu, a, off);
    if (lane == 0)
        atomicAdd(&out_scores[list[slot]], wlist[slot] * (a + b3[0]));
}

// ---------------- aux loss (deterministic 2-stage tree reduction) ----------
__global__ __launch_bounds__(256) void aux_partial(const float* __restrict__ probs,
                                                   float* __restrict__ partials)
{
    __shared__ float s[256][6];
    float acc[6] = {0.f, 0.f, 0.f, 0.f, 0.f, 0.f};
    int base = blockIdx.x * 384;                      // 256 blocks * 384 = NTOK
    for (int it = threadIdx.x; it < 384; it += 256) {
        const float* p = probs + (long)(base + it) * 6;
#pragma unroll
        for (int e = 0; e < 6; e++) acc[e] += p[e];
    }
#pragma unroll
    for (int e = 0; e < 6; e++) s[threadIdx.x][e] = acc[e];
    __syncthreads();
    for (int off = 128; off; off >>= 1) {
        if (threadIdx.x < off)
#pragma unroll
            for (int e = 0; e < 6; e++) s[threadIdx.x][e] += s[threadIdx.x + off][e];
        __syncthreads();
    }
    if (threadIdx.x < 6) partials[blockIdx.x * 6 + threadIdx.x] = s[0][threadIdx.x];
}

__global__ __launch_bounds__(256) void aux_final(const float* __restrict__ partials,
                                                 float* __restrict__ out_aux)
{
    __shared__ float s[256][6];
#pragma unroll
    for (int e = 0; e < 6; e++) s[threadIdx.x][e] = partials[threadIdx.x * 6 + e];
    __syncthreads();
    for (int off = 128; off; off >>= 1) {
        if (threadIdx.x < off)
#pragma unroll
            for (int e = 0; e < 6; e++) s[threadIdx.x][e] += s[threadIdx.x + off][e];
        __syncthreads();
    }
    if (threadIdx.x == 0) {
        float aux = 0.f;
#pragma unroll
        for (int e = 0; e < 6; e++) {
            float avg = s[0][e] / (float)NTOK;
            aux += avg * avg;
        }
        out_aux[0] = 6.f * aux;
    }
}

// ---------------------------- host launcher --------------------------------
extern "C" void kernel_launch(void* const* d_in, const int* in_sizes, int n_in,
                              void* d_out, int out_size)
{
    const float* x   = (const float*)d_in[0];
    const float* rW1 = (const float*)d_in[1];
    const float* rb1 = (const float*)d_in[2];
    const float* rW2 = (const float*)d_in[3];
    const float* rb2 = (const float*)d_in[4];
    const float* rW3 = (const float*)d_in[5];
    const float* rb3 = (const float*)d_in[6];
    const float* tW1 = (const float*)d_in[7];
    const float* tb1 = (const float*)d_in[8];
    const float* tW2 = (const float*)d_in[9];
    const float* tb2 = (const float*)d_in[10];
    const float* tW3 = (const float*)d_in[11];
    const float* tb3 = (const float*)d_in[12];
    const float* sW1 = (const float*)d_in[13];
    const float* sb1 = (const float*)d_in[14];
    const float* sW2 = (const float*)d_in[15];
    const float* sb2 = (const float*)d_in[16];
    const float* sW3 = (const float*)d_in[17];
    const float* sb3 = (const float*)d_in[18];
    float* out = (float*)d_out;

    float *H1, *H2, *G1, *G2, *S1, *S2, *wlist, *partials;
    int *list, *cnt;
    cudaGetSymbolAddress((void**)&H1, g_H1);
    cudaGetSymbolAddress((void**)&H2, g_H2);
    cudaGetSymbolAddress((void**)&G1, g_G1);
    cudaGetSymbolAddress((void**)&G2, g_G2);
    cudaGetSymbolAddress((void**)&S1, g_S1);
    cudaGetSymbolAddress((void**)&S2, g_S2);
    cudaGetSymbolAddress((void**)&list, g_list);
    cudaGetSymbolAddress((void**)&wlist, g_wlist);
    cudaGetSymbolAddress((void**)&cnt, g_cnt);
    cudaGetSymbolAddress((void**)&partials, g_partials);

    const int ROWB = NTOK / 64;  // 1536

    // 1. zero traj+score output regions and counters
    init_kernel<<<(TRAJ_LEN + NTOK) / 4 / 256, 256>>>(out);

    // 2. router MLP
    gemm_kernel<true, false><<<dim3(4, ROWB), 256>>>(x, 128, rW1, 256, rb1,
        H1, 256, 256, 128, nullptr, nullptr, NTOK);
    gemm_kernel<true, false><<<dim3(2, ROWB), 256>>>(H1, 256, rW2, 128, rb2,
        H2, 128, 128, 256, nullptr, nullptr, NTOK);
    router_tail<<<NTOK / 8, 256>>>(H2, rW3, rb3, out + PROBS_OFF, list, wlist, cnt);

    // 3. per-expert top-2 compute (dynamic counts read on device)
    for (int e = 0; e < EXP; e++) {
        const int* lst = list + e * NTOK;
        const float* wl = wlist + e * NTOK;
        const int* cp = cnt + e;
        // trajectory head: 128 -> 256 -> 256 -> 120
        gemm_kernel<true, true><<<dim3(4, ROWB), 256>>>(x, 128,
            tW1 + (long)e * 128 * 256, 256, tb1 + e * 256,
            G1, 256, 256, 128, lst, cp, 0);
        gemm_kernel<true, false><<<dim3(4, ROWB), 256>>>(G1, 256,
            tW2 + (long)e * 256 * 256, 256, tb2 + e * 256,
            G2, 256, 256, 256, nullptr, cp, 0);
        gemm_scatter_kernel<<<dim3(2, ROWB), 256>>>(G2, 256,
            tW3 + (long)e * 256 * 120, 120, tb3 + e * 120,
            out, 120, 256, lst, wl, cp);
        // score head: 128 -> 128 -> 64 -> 1
        gemm_kernel<true, true><<<dim3(2, ROWB), 256>>>(x, 128,
            sW1 + (long)e * 128 * 128, 128, sb1 + e * 128,
            S1, 128, 128, 128, lst, cp, 0);
        gemm_kernel<true, false><<<dim3(1, ROWB), 256>>>(S1, 128,
            sW2 + (long)e * 128 * 64, 64, sb2 + e * 64,
            S2, 64, 64, 128, nullptr, cp, 0);
        score_tail<<<NTOK / 8, 256>>>(S2, sW3 + e * 64, sb3 + e,
            lst, wl, cp, out + SCORE_OFF);
    }

    // 4. aux loss from probs
    aux_partial<<<256, 256>>>(out + PROBS_OFF, partials);
    aux_final<<<1, 256>>>(partials, out + AUX_OFF);
}

// round 2
// speedup vs baseline: 1.0528x; 1.0528x over previous
#include <cuda_runtime.h>
#include <math.h>

#define NTOK 98304              // B*M = 16384*6
#define EXP 6
#define TRAJ_LEN (NTOK*120)     // [B,M,T,2] = 11796480
#define SCORE_OFF TRAJ_LEN
#define AUX_OFF   (SCORE_OFF + NTOK)
#define PROBS_OFF (AUX_OFF + 1)

// ---------------- scratch (device globals; no allocation allowed) ----------
__device__ float g_H1[NTOK*256];     // router hidden 1
__device__ float g_H2[NTOK*128];     // router hidden 2
__device__ float g_G1[NTOK*256];     // expert traj hidden 1 (reused per expert)
__device__ float g_G2[NTOK*256];     // expert traj hidden 2
__device__ float g_S1[NTOK*128];     // expert score hidden 1
__device__ float g_S2[NTOK*64];      // expert score hidden 2
__device__ int   g_list[EXP*NTOK];   // token indices per expert
__device__ float g_wlist[EXP*NTOK];  // gate weight per (expert, slot)
__device__ int   g_cnt[8];           // tokens per expert
__device__ float g_partials[256*6];  // aux-loss partial sums

__device__ __forceinline__ float gelu_exact(float x) {
    return 0.5f * x * (1.0f + erff(x * 0.7071067811865476f));
}

// ---------------- init: zero accumulated output regions + counters ---------
__global__ void init_kernel(float* __restrict__ out) {
    long i = (long)blockIdx.x * blockDim.x + threadIdx.x;   // 11616*256 threads
    ((float4*)out)[i] = make_float4(0.f, 0.f, 0.f, 0.f);    // covers traj+scores
    if (blockIdx.x == 0 && threadIdx.x < 8) g_cnt[threadIdx.x] = 0;
}

// ---------------- generic tiled GEMM: C = act(A @ W + bias) ----------------
// A: [M,K] row-major (optionally gathered rows), W: [K,N] row-major.
// BM=BN=64, BK=16, 256 threads, 4x4 microtile.
template<bool GELU_ACT, bool GATHER>
__global__ __launch_bounds__(256) void gemm_kernel(
    const float* __restrict__ A, int lda,
    const float* __restrict__ W, int ldw,
    const float* __restrict__ bias,
    float* __restrict__ C, int ldc,
    int Ncols, int Kdim,
    const int* __restrict__ gather,
    const int* __restrict__ cntPtr, int Mfixed)
{
    int Mrows = cntPtr ? *cntPtr : Mfixed;
    int rowBase = blockIdx.y << 6;
    if (rowBase >= Mrows) return;
    int colBase = blockIdx.x << 6;

    __shared__ float As[16][64];
    __shared__ float Ws[16][64];

    int t  = threadIdx.x;
    int tx = t & 15, ty = t >> 4;

    // A-tile loader: thread covers (row mA, k-quad kqA)
    int mA = t & 63, kqA = t >> 6;
    int rowA = rowBase + mA;
    bool rowValid = rowA < Mrows;
    long arow = rowValid ? (GATHER ? (long)gather[rowA] : (long)rowA) : 0;
    const float* Aptr = A + arow * (long)lda;

    // W-tile loader
    int kW = t >> 4;
    int nW = (t & 15) << 2;
    int ncol = colBase + nW;
    bool colValid = ncol < Ncols;

    float acc[4][4];
#pragma unroll
    for (int i = 0; i < 4; i++)
#pragma unroll
        for (int j = 0; j < 4; j++) acc[i][j] = 0.f;

    for (int k0 = 0; k0 < Kdim; k0 += 16) {
        float4 av = rowValid ? *(const float4*)(Aptr + k0 + (kqA << 2))
                             : make_float4(0.f, 0.f, 0.f, 0.f);
        As[(kqA << 2) + 0][mA] = av.x;
        As[(kqA << 2) + 1][mA] = av.y;
        As[(kqA << 2) + 2][mA] = av.z;
        As[(kqA << 2) + 3][mA] = av.w;
        float4 wv = colValid ? *(const float4*)(W + (long)(k0 + kW) * ldw + ncol)
                             : make_float4(0.f, 0.f, 0.f, 0.f);
        *(float4*)&Ws[kW][nW] = wv;
        __syncthreads();
#pragma unroll
        for (int kk = 0; kk < 16; kk++) {
            float4 a = *(const float4*)&As[kk][ty << 2];
            float4 b = *(const float4*)&Ws[kk][tx << 2];
            acc[0][0] += a.x * b.x; acc[0][1] += a.x * b.y; acc[0][2] += a.x * b.z; acc[0][3] += a.x * b.w;
            acc[1][0] += a.y * b.x; acc[1][1] += a.y * b.y; acc[1][2] += a.y * b.z; acc[1][3] += a.y * b.w;
            acc[2][0] += a.z * b.x; acc[2][1] += a.z * b.y; acc[2][2] += a.z * b.z; acc[2][3] += a.z * b.w;
            acc[3][0] += a.w * b.x; acc[3][1] += a.w * b.y; acc[3][2] += a.w * b.z; acc[3][3] += a.w * b.w;
        }
        __syncthreads();
    }

    float bi[4];
#pragma unroll
    for (int j = 0; j < 4; j++) {
        int c = colBase + (tx << 2) + j;
        bi[j] = (c < Ncols) ? bias[c] : 0.f;
    }
#pragma unroll
    for (int i = 0; i < 4; i++) {
        int r = rowBase + (ty << 2) + i;
        if (r >= Mrows) continue;
        float* Crow = C + (long)r * ldc;
#pragma unroll
        for (int j = 0; j < 4; j++) {
            int c = colBase + (tx << 2) + j;
            if (c < Ncols) {
                float v = acc[i][j] + bi[j];
                if (GELU_ACT) v = gelu_exact(v);
                Crow[c] = v;
            }
        }
    }
}

// ---------------- traj final layer: GEMM + weighted scatter-add ------------
// out[token*120 + c] += w_slot * (G2[slot] @ W3 + b3)[c]
__global__ __launch_bounds__(256) void gemm_scatter_kernel(
    const float* __restrict__ A, int lda,
    const float* __restrict__ W, int ldw,
    const float* __restrict__ bias,
    float* __restrict__ out,
    int Ncols, int Kdim,
    const int* __restrict__ list,
    const float* __restrict__ wlist,
    const int* __restrict__ cntPtr)
{
    int Mrows = *cntPtr;
    int rowBase = blockIdx.y << 6;
    if (rowBase >= Mrows) return;
    int colBase = blockIdx.x << 6;

    __shared__ float As[16][64];
    __shared__ float Ws[16][64];

    int t  = threadIdx.x;
    int tx = t & 15, ty = t >> 4;

    int mA = t & 63, kqA = t >> 6;
    int rowA = rowBase + mA;
    bool rowValid = rowA < Mrows;
    const float* Aptr = A + (rowValid ? (long)rowA : 0L) * (long)lda;

    int kW = t >> 4;
    int nW = (t & 15) << 2;
    int ncol = colBase + nW;
    bool colValid = ncol < Ncols;

    float acc[4][4];
#pragma unroll
    for (int i = 0; i < 4; i++)
#pragma unroll
        for (int j = 0; j < 4; j++) acc[i][j] = 0.f;

    for (int k0 = 0; k0 < Kdim; k0 += 16) {
        float4 av = rowValid ? *(const float4*)(Aptr + k0 + (kqA << 2))
                             : make_float4(0.f, 0.f, 0.f, 0.f);
        As[(kqA << 2) + 0][mA] = av.x;
        As[(kqA << 2) + 1][mA] = av.y;
        As[(kqA << 2) + 2][mA] = av.z;
        As[(kqA << 2) + 3][mA] = av.w;
        float4 wv = colValid ? *(const float4*)(W + (long)(k0 + kW) * ldw + ncol)
                             : make_float4(0.f, 0.f, 0.f, 0.f);
        *(float4*)&Ws[kW][nW] = wv;
        __syncthreads();
#pragma unroll
        for (int kk = 0; kk < 16; kk++) {
            float4 a = *(const float4*)&As[kk][ty << 2];
            float4 b = *(const float4*)&Ws[kk][tx << 2];
            acc[0][0] += a.x * b.x; acc[0][1] += a.x * b.y; acc[0][2] += a.x * b.z; acc[0][3] += a.x * b.w;
            acc[1][0] += a.y * b.x; acc[1][1] += a.y * b.y; acc[1][2] += a.y * b.z; acc[1][3] += a.y * b.w;
            acc[2][0] += a.z * b.x; acc[2][1] += a.z * b.y; acc[2][2] += a.z * b.z; acc[2][3] += a.z * b.w;
            acc[3][0] += a.w * b.x; acc[3][1] += a.w * b.y; acc[3][2] += a.w * b.z; acc[3][3] += a.w * b.w;
        }
        __syncthreads();
    }

    float bi[4];
#pragma unroll
    for (int j = 0; j < 4; j++) {
        int c = colBase + (tx << 2) + j;
        bi[j] = (c < Ncols) ? bias[c] : 0.f;
    }
#pragma unroll
    for (int i = 0; i < 4; i++) {
        int slot = rowBase + (ty << 2) + i;
        if (slot >= Mrows) continue;
        int token = list[slot];
        float w   = wlist[slot];
        float* orow = out + (long)token * 120;
#pragma unroll
        for (int j = 0; j < 4; j++) {
            int c = colBase + (tx << 2) + j;
            if (c < Ncols) atomicAdd(&orow[c], w * (acc[i][j] + bi[j]));
        }
    }
}

// ---------------- router tail: logits -> probs, top-2 gate, expert lists ---
__global__ __launch_bounds__(256) void router_tail(
    const float* __restrict__ H2,
    const float* __restrict__ W3,   // [128,6]
    const float* __restrict__ b3,   // [6]
    float* __restrict__ probs_out,  // [NTOK,6]
    int*   __restrict__ lists,
    float* __restrict__ wlists,
    int*   __restrict__ cnts)
{
    __shared__ float sW[128*6];
    __shared__ float sb[6];
    for (int i = threadIdx.x; i < 128*6; i += 256) sW[i] = W3[i];
    if (threadIdx.x < 6) sb[threadIdx.x] = b3[threadIdx.x];
    __syncthreads();

    int warp = threadIdx.x >> 5;
    int lane = threadIdx.x & 31;
    int token = blockIdx.x * 8 + warp;
    if (token >= NTOK) return;

    const float* h = H2 + (long)token * 128;
    float acc[6] = {0.f, 0.f, 0.f, 0.f, 0.f, 0.f};
#pragma unroll
    for (int j = 0; j < 4; j++) {
        int k = lane + 32 * j;
        float xv = h[k];
#pragma unroll
        for (int e = 0; e < 6; e++) acc[e] += xv * sW[k*6 + e];
    }
#pragma unroll
    for (int off = 16; off; off >>= 1)
#pragma unroll
        for (int e = 0; e < 6; e++) acc[e] += __shfl_xor_sync(0xffffffffu, acc[e], off);

    if (lane == 0) {
        float logits[6];
#pragma unroll
        for (int e = 0; e < 6; e++) logits[e] = acc[e] + sb[e];
        // full softmax -> probs
        float mx = logits[0];
#pragma unroll
        for (int e = 1; e < 6; e++) mx = fmaxf(mx, logits[e]);
        float p[6], s = 0.f;
#pragma unroll
        for (int e = 0; e < 6; e++) { p[e] = expf(logits[e] - mx); s += p[e]; }
        float inv = 1.f / s;
#pragma unroll
        for (int e = 0; e < 6; e++) probs_out[(long)token*6 + e] = p[e] * inv;
        // top-2 (ties -> lowest index, matching lax.top_k)
        int i0 = 0;
#pragma unroll
        for (int e = 1; e < 6; e++) if (logits[e] > logits[i0]) i0 = e;
        int i1 = (i0 == 0) ? 1 : 0;
#pragma unroll
        for (int e = 0; e < 6; e++)
            if (e != i0 && logits[e] > logits[i1]) i1 = e;
        float r  = expf(logits[i1] - logits[i0]);
        float w0 = 1.f / (1.f + r);
        float w1 = r / (1.f + r);
        int s0 = atomicAdd(&cnts[i0], 1);
        lists[i0*NTOK + s0] = token;  wlists[i0*NTOK + s0] = w0;
        int s1 = atomicAdd(&cnts[i1], 1);
        lists[i1*NTOK + s1] = token;  wlists[i1*NTOK + s1] = w1;
    }
}

// ---------------- score tail: dot(S2[slot], W3) + b; scatter-add -----------
__global__ __launch_bounds__(256) void score_tail(
    const float* __restrict__ S2,
    const float* __restrict__ W3,   // [64]
    const float* __restrict__ b3,   // [1]
    const int*   __restrict__ list,
    const float* __restrict__ wlist,
    const int*   __restrict__ cntPtr,
    float* __restrict__ out_scores)
{
    __shared__ float sW[64];
    if (threadIdx.x < 64) sW[threadIdx.x] = W3[threadIdx.x];
    __syncthreads();
    int cnt = *cntPtr;
    int warp = threadIdx.x >> 5;
    int lane = threadIdx.x & 31;
    int slot = blockIdx.x * 8 + warp;
    if (slot >= cnt) return;
    const float* row = S2 + (long)slot * 64;
    float a = row[lane] * sW[lane] + row[lane + 32] * sW[lane + 32];
#pragma unroll
    for (int off = 16; off; off >>= 1) a += __shfl_xor_sync(0xffffffffu, a, off);
    if (lane == 0)
        atomicAdd(&out_scores[list[slot]], wlist[slot] * (a + b3[0]));
}

// ---------------- aux loss (deterministic 2-stage tree reduction) ----------
__global__ __launch_bounds__(256) void aux_partial(const float* __restrict__ probs,
                                                   float* __restrict__ partials)
{
    __shared__ float s[256][6];
    float acc[6] = {0.f, 0.f, 0.f, 0.f, 0.f, 0.f};
    int base = blockIdx.x * 384;                      // 256 blocks * 384 = NTOK
    for (int it = threadIdx.x; it < 384; it += 256) {
        const float* p = probs + (long)(base + it) * 6;
#pragma unroll
        for (int e = 0; e < 6; e++) acc[e] += p[e];
    }
#pragma unroll
    for (int e = 0; e < 6; e++) s[threadIdx.x][e] = acc[e];
    __syncthreads();
    for (int off = 128; off; off >>= 1) {
        if (threadIdx.x < off)
#pragma unroll
            for (int e = 0; e < 6; e++) s[threadIdx.x][e] += s[threadIdx.x + off][e];
        __syncthreads();
    }
    if (threadIdx.x < 6) partials[blockIdx.x * 6 + threadIdx.x] = s[0][threadIdx.x];
}

__global__ __launch_bounds__(256) void aux_final(const float* __restrict__ partials,
                                                 float* __restrict__ out_aux)
{
    __shared__ float s[256][6];
#pragma unroll
    for (int e = 0; e < 6; e++) s[threadIdx.x][e] = partials[threadIdx.x * 6 + e];
    __syncthreads();
    for (int off = 128; off; off >>= 1) {
        if (threadIdx.x < off)
#pragma unroll
            for (int e = 0; e < 6; e++) s[threadIdx.x][e] += s[threadIdx.x + off][e];
        __syncthreads();
    }
    if (threadIdx.x == 0) {
        float aux = 0.f;
#pragma unroll
        for (int e = 0; e < 6; e++) {
            float avg = s[0][e] / (float)NTOK;
            aux += avg * avg;
        }
        out_aux[0] = 6.f * aux;
    }
}

// ---------------------------- host launcher --------------------------------
extern "C" void kernel_launch(void* const* d_in, const int* in_sizes, int n_in,
                              void* d_out, int out_size)
{
    const float* x   = (const float*)d_in[0];
    const float* rW1 = (const float*)d_in[1];
    const float* rb1 = (const float*)d_in[2];
    const float* rW2 = (const float*)d_in[3];
    const float* rb2 = (const float*)d_in[4];
    const float* rW3 = (const float*)d_in[5];
    const float* rb3 = (const float*)d_in[6];
    const float* tW1 = (const float*)d_in[7];
    const float* tb1 = (const float*)d_in[8];
    const float* tW2 = (const float*)d_in[9];
    const float* tb2 = (const float*)d_in[10];
    const float* tW3 = (const float*)d_in[11];
    const float* tb3 = (const float*)d_in[12];
    const float* sW1 = (const float*)d_in[13];
    const float* sb1 = (const float*)d_in[14];
    const float* sW2 = (const float*)d_in[15];
    const float* sb2 = (const float*)d_in[16];
    const float* sW3 = (const float*)d_in[17];
    const float* sb3 = (const float*)d_in[18];
    float* out = (float*)d_out;

    float *H1, *H2, *G1, *G2, *S1, *S2, *wlist, *partials;
    int *list, *cnt;
    cudaGetSymbolAddress((void**)&H1, g_H1);
    cudaGetSymbolAddress((void**)&H2, g_H2);
    cudaGetSymbolAddress((void**)&G1, g_G1);
    cudaGetSymbolAddress((void**)&G2, g_G2);
    cudaGetSymbolAddress((void**)&S1, g_S1);
    cudaGetSymbolAddress((void**)&S2, g_S2);
    cudaGetSymbolAddress((void**)&list, g_list);
    cudaGetSymbolAddress((void**)&wlist, g_wlist);
    cudaGetSymbolAddress((void**)&cnt, g_cnt);
    cudaGetSymbolAddress((void**)&partials, g_partials);

    const int ROWB = NTOK / 64;  // 1536

    // 1. zero traj+score output regions and counters
    init_kernel<<<(TRAJ_LEN + NTOK) / 4 / 256, 256>>>(out);

    // 2. router MLP
    gemm_kernel<true, false><<<dim3(4, ROWB), 256>>>(x, 128, rW1, 256, rb1,
        H1, 256, 256, 128, nullptr, nullptr, NTOK);
    gemm_kernel<true, false><<<dim3(2, ROWB), 256>>>(H1, 256, rW2, 128, rb2,
        H2, 128, 128, 256, nullptr, nullptr, NTOK);
    router_tail<<<NTOK / 8, 256>>>(H2, rW3, rb3, out + PROBS_OFF, list, wlist, cnt);

    // 3. per-expert top-2 compute (dynamic counts read on device)
    for (int e = 0; e < EXP; e++) {
        const int* lst = list + e * NTOK;
        const float* wl = wlist + e * NTOK;
        const int* cp = cnt + e;
        // trajectory head: 128 -> 256 -> 256 -> 120
        gemm_kernel<true, true><<<dim3(4, ROWB), 256>>>(x, 128,
            tW1 + (long)e * 128 * 256, 256, tb1 + e * 256,
            G1, 256, 256, 128, lst, cp, 0);
        gemm_kernel<true, false><<<dim3(4, ROWB), 256>>>(G1, 256,
            tW2 + (long)e * 256 * 256, 256, tb2 + e * 256,
            G2, 256, 256, 256, nullptr, cp, 0);
        gemm_scatter_kernel<<<dim3(2, ROWB), 256>>>(G2, 256,
            tW3 + (long)e * 256 * 120, 120, tb3 + e * 120,
            out, 120, 256, lst, wl, cp);
        // score head: 128 -> 128 -> 64 -> 1
        gemm_kernel<true, true><<<dim3(2, ROWB), 256>>>(x, 128,
            sW1 + (long)e * 128 * 128, 128, sb1 + e * 128,
            S1, 128, 128, 128, lst, cp, 0);
        gemm_kernel<true, false><<<dim3(1, ROWB), 256>>>(S1, 128,
            sW2 + (long)e * 128 * 64, 64, sb2 + e * 64,
            S2, 64, 64, 128, nullptr, cp, 0);
        score_tail<<<NTOK / 8, 256>>>(S2, sW3 + e * 64, sb3 + e,
            lst, wl, cp, out + SCORE_OFF);
    }

    // 4. aux loss from probs
    aux_partial<<<256, 256>>>(out + PROBS_OFF, partials);
    aux_final<<<1, 256>>>(partials, out + AUX_OFF);
}